// round 1
// baseline (speedup 1.0000x reference)
#include <cuda_runtime.h>
#include <cuda_bf16.h>

#define Bsz 16384
#define Fn 26
#define Nrows 100000
#define Dim 64
#define Lk 4
#define NFEAT 27              // 1 dense + 26 pooled
#define NPAIRS 351            // 27*26/2
#define OVERIN 415            // 64 + 351

// ---------------- scratch (device globals; no allocation allowed) ----------
__device__ float g_h1[Bsz * 512];          // bottom h1 / top t1
__device__ float g_h2[Bsz * 256];          // bottom h2 / top t2
__device__ float g_feats[Bsz * NFEAT * Dim]; // (B, 27, 64)
__device__ float g_yin[Bsz * OVERIN];      // (B, 415)

// ---------------- generic tiled GEMM: C = act(A(MxK) @ W(KxN) + bias) ------
#define BM 64
#define BN 64
#define BK 16

__global__ __launch_bounds__(256)
void gemm_bias_act(const float* __restrict__ A, const float* __restrict__ W,
                   const float* __restrict__ bias, float* __restrict__ C,
                   int M, int N, int K, int ldc, int relu)
{
    __shared__ float As[BK][BM + 1];
    __shared__ float Ws[BK][BN];

    const int bm = blockIdx.y * BM;
    const int bn = blockIdx.x * BN;
    const int tid = threadIdx.x;
    const int tx = tid & 15;          // 0..15 -> N direction
    const int ty = tid >> 4;          // 0..15 -> M direction

    float acc[4][4] = {};

    for (int k0 = 0; k0 < K; k0 += BK) {
        // load A tile (BM x BK), coalesced on K
        #pragma unroll
        for (int i = tid; i < BM * BK; i += 256) {
            int r = i >> 4;           // 0..63
            int c = i & 15;           // 0..15
            int gr = bm + r, gc = k0 + c;
            float v = 0.f;
            if (gr < M && gc < K) v = A[(long long)gr * K + gc];
            As[c][r] = v;
        }
        // load W tile (BK x BN), coalesced on N
        #pragma unroll
        for (int i = tid; i < BK * BN; i += 256) {
            int r = i >> 6;           // 0..15
            int c = i & 63;           // 0..63
            int gr = k0 + r, gc = bn + c;
            float v = 0.f;
            if (gr < K && gc < N) v = W[(long long)gr * N + gc];
            Ws[r][c] = v;
        }
        __syncthreads();

        #pragma unroll
        for (int kk = 0; kk < BK; kk++) {
            float a[4], w[4];
            #pragma unroll
            for (int i = 0; i < 4; i++) a[i] = As[kk][ty * 4 + i];
            #pragma unroll
            for (int j = 0; j < 4; j++) w[j] = Ws[kk][tx * 4 + j];
            #pragma unroll
            for (int i = 0; i < 4; i++)
                #pragma unroll
                for (int j = 0; j < 4; j++)
                    acc[i][j] = fmaf(a[i], w[j], acc[i][j]);
        }
        __syncthreads();
    }

    #pragma unroll
    for (int i = 0; i < 4; i++) {
        int gr = bm + ty * 4 + i;
        if (gr >= M) continue;
        #pragma unroll
        for (int j = 0; j < 4; j++) {
            int gc = bn + tx * 4 + j;
            if (gc >= N) continue;
            float v = acc[i][j] + bias[gc];
            if (relu) v = fmaxf(v, 0.f);
            C[(long long)gr * ldc + gc] = v;
        }
    }
}

// ---------------- embedding gather + pool: one warp per (f, b) -------------
// Writes pooled[f][b] into g_feats[b][1+f][:].
// Auto-detects index dtype (int32 vs int64) by sampling: an int64 view of
// int32 data gives values >= Nrows unless the paired hi-word index is 0
// (P = 1e-5 per sample; 4 samples -> ~1e-20 false positive).
__global__ __launch_bounds__(256)
void gather_pool(const void* __restrict__ idx_raw,
                 const float* __restrict__ tables,
                 float* __restrict__ feats)
{
    const int gwarp = (blockIdx.x * blockDim.x + threadIdx.x) >> 5;
    const int lane = threadIdx.x & 31;
    if (gwarp >= Fn * Bsz) return;
    const int f = gwarp / Bsz;
    const int b = gwarp % Bsz;

    const long long* p64 = (const long long*)idx_raw;
    long long v0 = p64[0], v1 = p64[123], v2 = p64[4567], v3 = p64[89012];
    const bool is64 = (v0 >= 0 && v0 < Nrows) && (v1 >= 0 && v1 < Nrows) &&
                      (v2 >= 0 && v2 < Nrows) && (v3 >= 0 && v3 < Nrows);

    const long long base = (long long)f * Bsz * Lk + (long long)b * Lk;
    const int* p32 = (const int*)idx_raw;

    float2 acc = make_float2(0.f, 0.f);
    #pragma unroll
    for (int l = 0; l < Lk; l++) {
        long long row = is64 ? p64[base + l] : (long long)p32[base + l];
        const float2* src = (const float2*)(tables +
                             ((long long)f * Nrows + row) * Dim);
        float2 v = src[lane];
        acc.x += v.x; acc.y += v.y;
    }
    float2* dst = (float2*)(feats + (long long)b * (NFEAT * Dim) + (f + 1) * Dim);
    dst[lane] = acc;
}

// ---------------- interaction: triu(feats @ feats^T), concat with dense ----
__global__ __launch_bounds__(128)
void interact(const float* __restrict__ feats, float* __restrict__ yin)
{
    __shared__ float fs[NFEAT * 65];   // pad to 65 to kill bank conflicts
    const int b = blockIdx.x;
    const float* frow = feats + (long long)b * (NFEAT * Dim);

    for (int i = threadIdx.x; i < NFEAT * Dim; i += blockDim.x) {
        int r = i >> 6, c = i & 63;
        fs[r * 65 + c] = frow[i];
    }
    __syncthreads();

    float* yrow = yin + (long long)b * OVERIN;
    for (int i = threadIdx.x; i < Dim; i += blockDim.x)
        yrow[i] = fs[i];                        // dense part (feature 0)

    for (int p = threadIdx.x; p < NPAIRS; p += blockDim.x) {
        int i = 0, rem = p;
        while (rem >= (Fn + 1) - 1 - i) { rem -= (Fn + 1) - 1 - i; i++; }
        int j = i + 1 + rem;                    // row-major triu order (k=1)
        const float* fi = fs + i * 65;
        const float* fj = fs + j * 65;
        float s = 0.f;
        #pragma unroll
        for (int k = 0; k < Dim; k++) s = fmaf(fi[k], fj[k], s);
        yrow[Dim + p] = s;
    }
}

// ---------------- final layer: (B,256) @ (256,1) + bias, one warp per row --
__global__ __launch_bounds__(256)
void gemv_final(const float* __restrict__ X, const float* __restrict__ w,
                const float* __restrict__ bias, float* __restrict__ out)
{
    const int row = (blockIdx.x * blockDim.x + threadIdx.x) >> 5;
    const int lane = threadIdx.x & 31;
    if (row >= Bsz) return;
    const float* x = X + (long long)row * 256;
    float s = 0.f;
    #pragma unroll
    for (int k = lane; k < 256; k += 32) s = fmaf(x[k], w[k], s);
    #pragma unroll
    for (int o = 16; o; o >>= 1) s += __shfl_down_sync(0xffffffffu, s, o);
    if (lane == 0) out[row] = s + bias[0];
}

// ---------------------------------------------------------------------------
static void* sym_addr(const void* sym)
{
    void* p = nullptr;
    cudaGetSymbolAddress(&p, sym);
    return p;
}

extern "C" void kernel_launch(void* const* d_in, const int* in_sizes, int n_in,
                              void* d_out, int out_size)
{
    (void)in_sizes; (void)n_in; (void)out_size;

    const float* dense   = (const float*)d_in[0];
    const void*  sp_idx  = d_in[1];
    const float* tables  = (const float*)d_in[2];
    const float* botW0   = (const float*)d_in[3];
    const float* botb0   = (const float*)d_in[4];
    const float* botW1   = (const float*)d_in[5];
    const float* botb1   = (const float*)d_in[6];
    const float* botW2   = (const float*)d_in[7];
    const float* botb2   = (const float*)d_in[8];
    const float* topW0   = (const float*)d_in[9];
    const float* topb0   = (const float*)d_in[10];
    const float* topW1   = (const float*)d_in[11];
    const float* topb1   = (const float*)d_in[12];
    const float* topW2   = (const float*)d_in[13];
    const float* topb2   = (const float*)d_in[14];
    float* out = (float*)d_out;

    float* h1    = (float*)sym_addr(g_h1);
    float* h2    = (float*)sym_addr(g_h2);
    float* feats = (float*)sym_addr(g_feats);
    float* yin   = (float*)sym_addr(g_yin);

    const dim3 blk(256);

    // Bottom MLP: 13 -> 512 -> 256 -> 64 (relu each), last writes feats[:,0,:]
    {
        dim3 g0((512 + BN - 1) / BN, (Bsz + BM - 1) / BM);
        gemm_bias_act<<<g0, blk>>>(dense, botW0, botb0, h1, Bsz, 512, 13, 512, 1);
        dim3 g1((256 + BN - 1) / BN, (Bsz + BM - 1) / BM);
        gemm_bias_act<<<g1, blk>>>(h1, botW1, botb1, h2, Bsz, 256, 512, 256, 1);
        dim3 g2((64 + BN - 1) / BN, (Bsz + BM - 1) / BM);
        gemm_bias_act<<<g2, blk>>>(h2, botW2, botb2, feats, Bsz, 64, 256,
                                   NFEAT * Dim, 1);
    }

    // Embedding gather + pool into feats[:,1..26,:]
    {
        int total_warps = Fn * Bsz;
        int nblocks = (total_warps * 32 + 255) / 256;
        gather_pool<<<nblocks, blk>>>(sp_idx, tables, feats);
    }

    // Pairwise interaction -> yin (B, 415)
    interact<<<Bsz, 128>>>(feats, yin);

    // Top MLP: 415 -> 512 (relu) -> 256 (relu) -> 1
    {
        dim3 g0((512 + BN - 1) / BN, (Bsz + BM - 1) / BM);
        gemm_bias_act<<<g0, blk>>>(yin, topW0, topb0, h1, Bsz, 512, OVERIN, 512, 1);
        dim3 g1((256 + BN - 1) / BN, (Bsz + BM - 1) / BM);
        gemm_bias_act<<<g1, blk>>>(h1, topW1, topb1, h2, Bsz, 256, 512, 256, 1);
        gemv_final<<<(Bsz * 32 + 255) / 256, blk>>>(h2, topW2, topb2, out);
    }
}

// round 2
// speedup vs baseline: 1.0798x; 1.0798x over previous
#include <cuda_runtime.h>
#include <cuda_bf16.h>

#define Bsz 16384
#define Fn 26
#define Nrows 100000
#define Dim 64
#define Lk 4
#define NFEAT 27              // 1 dense + 26 pooled
#define NPAIRS 351            // 27*26/2
#define OVERIN 415            // 64 + 351

// ---------------- scratch (device globals; no allocation allowed) ----------
__device__ float g_h1[Bsz * 512];          // bottom h1 / top t1
__device__ float g_h2[Bsz * 256];          // bottom h2 / top t2
__device__ float g_dense[Bsz * Dim];       // bottom MLP output (B, 64)
__device__ float g_yin[Bsz * OVERIN];      // (B, 415)

// ---------------- tiled GEMM: C = act(A(MxK) @ W(KxN) + bias) --------------
// 128x64 tile, 256 threads, 8x4 per-thread fragment, BK=16.
#define GBM 128
#define GBN 64
#define GBK 16

__global__ __launch_bounds__(256)
void gemm_bias_act(const float* __restrict__ A, const float* __restrict__ W,
                   const float* __restrict__ bias, float* __restrict__ C,
                   int M, int N, int K, int ldc, int relu)
{
    __shared__ float As[GBK][GBM + 4];
    __shared__ float Ws[GBK][GBN];

    const int bm = blockIdx.y * GBM;
    const int bn = blockIdx.x * GBN;
    const int tid = threadIdx.x;
    const int tx = tid & 15;          // N direction: 16 * 4 = 64
    const int ty = tid >> 4;          // M direction: 16 * 8 = 128

    float acc[8][4] = {};

    for (int k0 = 0; k0 < K; k0 += GBK) {
        // A tile (GBM x GBK): 2048 elems, 8 per thread, coalesced on K
        #pragma unroll
        for (int s = 0; s < 8; s++) {
            int i = tid + s * 256;
            int r = i >> 4;           // 0..127
            int c = i & 15;           // 0..15
            int gr = bm + r, gc = k0 + c;
            float v = 0.f;
            if (gc < K) v = A[(long long)gr * K + gc];   // gr < M always (M%128==0)
            As[c][r] = v;
        }
        // W tile (GBK x GBN): 1024 elems, 4 per thread, coalesced on N
        #pragma unroll
        for (int s = 0; s < 4; s++) {
            int i = tid + s * 256;
            int r = i >> 6;           // 0..15
            int c = i & 63;           // 0..63
            int gr = k0 + r, gc = bn + c;
            float v = 0.f;
            if (gr < K && gc < N) v = W[(long long)gr * N + gc];
            Ws[r][c] = v;
        }
        __syncthreads();

        #pragma unroll
        for (int kk = 0; kk < GBK; kk++) {
            float a[8], w[4];
            #pragma unroll
            for (int i = 0; i < 8; i++) a[i] = As[kk][ty * 8 + i];
            #pragma unroll
            for (int j = 0; j < 4; j++) w[j] = Ws[kk][tx * 4 + j];
            #pragma unroll
            for (int i = 0; i < 8; i++)
                #pragma unroll
                for (int j = 0; j < 4; j++)
                    acc[i][j] = fmaf(a[i], w[j], acc[i][j]);
        }
        __syncthreads();
    }

    float bv[4];
    #pragma unroll
    for (int j = 0; j < 4; j++) {
        int gc = bn + tx * 4 + j;
        bv[j] = (gc < N) ? bias[gc] : 0.f;
    }
    #pragma unroll
    for (int i = 0; i < 8; i++) {
        int gr = bm + ty * 8 + i;
        #pragma unroll
        for (int j = 0; j < 4; j++) {
            int gc = bn + tx * 4 + j;
            if (gc >= N) continue;
            float v = acc[i][j] + bv[j];
            if (relu) v = fmaxf(v, 0.f);
            C[(long long)gr * ldc + gc] = v;
        }
    }
}

// -------- fused gather+pool+interaction: one block (128 thr) per sample ----
// fs[0] = dense output row; fs[1..26] = pooled embeddings; then triu dots.
// Index dtype auto-detected (int32 vs int64) by sampling.
__global__ __launch_bounds__(128)
void gather_interact(const void* __restrict__ idx_raw,
                     const float* __restrict__ tables,
                     const float* __restrict__ dense,
                     float* __restrict__ yin)
{
    __shared__ float fs[NFEAT * 65];   // padded rows: no bank conflicts
    const int b = blockIdx.x;
    const int tid = threadIdx.x;
    const int warp = tid >> 5;
    const int lane = tid & 31;

    // dense output -> fs[0]
    if (tid < Dim) fs[tid] = dense[(long long)b * Dim + tid];

    // detect index width
    const long long* p64 = (const long long*)idx_raw;
    long long v0 = p64[0], v1 = p64[123], v2 = p64[4567], v3 = p64[89012];
    const bool is64 = (v0 >= 0 && v0 < Nrows) && (v1 >= 0 && v1 < Nrows) &&
                      (v2 >= 0 && v2 < Nrows) && (v3 >= 0 && v3 < Nrows);
    const int* p32 = (const int*)idx_raw;

    // gather + pool: warp w handles features w, w+4, ...
    for (int f = warp; f < Fn; f += 4) {
        const long long base = (long long)f * Bsz * Lk + (long long)b * Lk;
        float2 acc = make_float2(0.f, 0.f);
        #pragma unroll
        for (int l = 0; l < Lk; l++) {
            long long row = is64 ? p64[base + l] : (long long)p32[base + l];
            const float2* src = (const float2*)(tables +
                                 ((long long)f * Nrows + row) * Dim);
            float2 v = src[lane];
            acc.x += v.x; acc.y += v.y;
        }
        fs[(f + 1) * 65 + lane * 2]     = acc.x;
        fs[(f + 1) * 65 + lane * 2 + 1] = acc.y;
    }
    __syncthreads();

    float* yrow = yin + (long long)b * OVERIN;
    for (int i = tid; i < Dim; i += 128) yrow[i] = fs[i];

    for (int p = tid; p < NPAIRS; p += 128) {
        int i = 0, rem = p;
        while (rem >= NFEAT - 1 - i) { rem -= NFEAT - 1 - i; i++; }
        int j = i + 1 + rem;                    // row-major triu (k=1)
        const float* fi = fs + i * 65;
        const float* fj = fs + j * 65;
        float s = 0.f;
        #pragma unroll
        for (int k = 0; k < Dim; k++) s = fmaf(fi[k], fj[k], s);
        yrow[Dim + p] = s;
    }
}

// ---------------- final layer: (B,256) @ (256,1) + bias, warp per row ------
__global__ __launch_bounds__(256)
void gemv_final(const float* __restrict__ X, const float* __restrict__ w,
                const float* __restrict__ bias, float* __restrict__ out)
{
    const int row = (blockIdx.x * blockDim.x + threadIdx.x) >> 5;
    const int lane = threadIdx.x & 31;
    if (row >= Bsz) return;
    const float4* x = (const float4*)(X + (long long)row * 256);
    const float4* wv = (const float4*)w;
    float s = 0.f;
    #pragma unroll
    for (int k = lane; k < 64; k += 32) {
        float4 a = x[k], c = wv[k];
        s = fmaf(a.x, c.x, s); s = fmaf(a.y, c.y, s);
        s = fmaf(a.z, c.z, s); s = fmaf(a.w, c.w, s);
    }
    #pragma unroll
    for (int o = 16; o; o >>= 1) s += __shfl_down_sync(0xffffffffu, s, o);
    if (lane == 0) out[row] = s + bias[0];
}

// ---------------------------------------------------------------------------
static void* sym_addr(const void* sym)
{
    void* p = nullptr;
    cudaGetSymbolAddress(&p, sym);
    return p;
}

extern "C" void kernel_launch(void* const* d_in, const int* in_sizes, int n_in,
                              void* d_out, int out_size)
{
    (void)in_sizes; (void)n_in; (void)out_size;

    const float* dense   = (const float*)d_in[0];
    const void*  sp_idx  = d_in[1];
    const float* tables  = (const float*)d_in[2];
    const float* botW0   = (const float*)d_in[3];
    const float* botb0   = (const float*)d_in[4];
    const float* botW1   = (const float*)d_in[5];
    const float* botb1   = (const float*)d_in[6];
    const float* botW2   = (const float*)d_in[7];
    const float* botb2   = (const float*)d_in[8];
    const float* topW0   = (const float*)d_in[9];
    const float* topb0   = (const float*)d_in[10];
    const float* topW1   = (const float*)d_in[11];
    const float* topb1   = (const float*)d_in[12];
    const float* topW2   = (const float*)d_in[13];
    const float* topb2   = (const float*)d_in[14];
    float* out = (float*)d_out;

    float* h1  = (float*)sym_addr(g_h1);
    float* h2  = (float*)sym_addr(g_h2);
    float* dns = (float*)sym_addr(g_dense);
    float* yin = (float*)sym_addr(g_yin);

    const dim3 blk(256);
    const int MB = Bsz / GBM;   // 128 M-blocks

    // Bottom MLP: 13 -> 512 -> 256 -> 64 (relu each)
    gemm_bias_act<<<dim3(512 / GBN, MB), blk>>>(dense, botW0, botb0, h1,
                                                Bsz, 512, 13, 512, 1);
    gemm_bias_act<<<dim3(256 / GBN, MB), blk>>>(h1, botW1, botb1, h2,
                                                Bsz, 256, 512, 256, 1);
    gemm_bias_act<<<dim3(64 / GBN, MB), blk>>>(h2, botW2, botb2, dns,
                                               Bsz, 64, 256, 64, 1);

    // Fused embedding gather + pool + pairwise interaction -> yin (B, 415)
    gather_interact<<<Bsz, 128>>>(sp_idx, tables, dns, yin);

    // Top MLP: 415 -> 512 (relu) -> 256 (relu) -> 1
    gemm_bias_act<<<dim3(512 / GBN, MB), blk>>>(yin, topW0, topb0, h1,
                                                Bsz, 512, OVERIN, 512, 1);
    gemm_bias_act<<<dim3(256 / GBN, MB), blk>>>(h1, topW1, topb1, h2,
                                                Bsz, 256, 512, 256, 1);
    gemv_final<<<(Bsz * 32 + 255) / 256, blk>>>(h2, topW2, topb2, out);
}

// round 4
// speedup vs baseline: 1.4923x; 1.3819x over previous
#include <cuda_runtime.h>
#include <cuda_bf16.h>
#include <cstdint>

#define Bsz 16384
#define Fn 26
#define Nrows 100000
#define Dim 64
#define Lk 4
#define NFEAT 27              // 1 dense + 26 pooled
#define NPAIRS 351            // 27*26/2
#define OVERIN 415            // 64 + 351

// ---------------- scratch (device globals; no allocation allowed) ----------
__device__ float g_h1[Bsz * 512];
__device__ float g_h2[Bsz * 256];
__device__ float g_feats[Bsz * NFEAT * Dim]; // (B, 27, 64)
__device__ float g_yin[Bsz * OVERIN];        // (B, 415)

// ---------------- mma.sync helpers -----------------------------------------
#define MMA_BF16(c, a, b) \
    asm volatile("mma.sync.aligned.m16n8k16.row.col.f32.bf16.bf16.f32 " \
        "{%0,%1,%2,%3}, {%4,%5,%6,%7}, {%8,%9}, {%0,%1,%2,%3};" \
        : "+f"((c)[0]), "+f"((c)[1]), "+f"((c)[2]), "+f"((c)[3]) \
        : "r"((a)[0]), "r"((a)[1]), "r"((a)[2]), "r"((a)[3]), \
          "r"((b)[0]), "r"((b)[1]))

__device__ __forceinline__ void split2(float x0, float x1,
                                       uint32_t& hi, uint32_t& lo)
{
    __nv_bfloat162 h, l;
    h.x = __float2bfloat16(x0);
    h.y = __float2bfloat16(x1);
    l.x = __float2bfloat16(x0 - __bfloat162float(h.x));
    l.y = __float2bfloat16(x1 - __bfloat162float(h.y));
    hi = *(uint32_t*)&h;
    lo = *(uint32_t*)&l;
}

// ============ tensor-core GEMM: C = act(A(MxK) @ W(KxN) + bias) =============
// CTA tile 128x64, 256 thr (8 warps = 4M x 2N), warp tile 32x32, K-chunk 32.
// Split-bf16 (hi+lo) 3-term products for near-fp32 accuracy.
#define LDA 40   // bf16 elements per smem row (80B = 20 banks: conflict-free frags)

__global__ __launch_bounds__(256)
void gemm_mma(const float* __restrict__ A, const float* __restrict__ W,
              const float* __restrict__ bias, float* __restrict__ C,
              int K, int N, int ldc, int relu)
{
    __shared__ __nv_bfloat16 As[2][128 * LDA];   // [plane hi/lo][r*LDA + k]
    __shared__ __nv_bfloat16 Bs[2][64 * LDA];    // [plane][n*LDA + k]

    const int tid  = threadIdx.x;
    const int warp = tid >> 5, lane = tid & 31;
    const int wm = warp & 3, wn = warp >> 2;      // warp grid 4(M) x 2(N)
    const int gid = lane >> 2, tig = lane & 3;
    const int bm = blockIdx.y * 128, bn = blockIdx.x * 64;

    float acc[2][4][4];
    #pragma unroll
    for (int mt = 0; mt < 2; mt++)
        #pragma unroll
        for (int nt = 0; nt < 4; nt++)
            #pragma unroll
            for (int e = 0; e < 4; e++) acc[mt][nt][e] = 0.f;

    const int kIter = (K + 31) / 32;
    for (int it = 0; it < kIter; it++) {
        const int k0 = it * 32;

        // ---- producer: A chunk 128x32 fp32 -> hi/lo bf16 (2048 pairs) ----
        #pragma unroll
        for (int s = 0; s < 8; s++) {
            int p = tid + s * 256;
            int r = p >> 4;
            int c2 = (p & 15) * 2;
            int gk = k0 + c2;
            const float* ar = A + (long long)(bm + r) * K;
            float x0 = (gk < K)     ? __ldg(ar + gk)     : 0.f;
            float x1 = (gk + 1 < K) ? __ldg(ar + gk + 1) : 0.f;
            uint32_t hi, lo;
            split2(x0, x1, hi, lo);
            *(uint32_t*)&As[0][r * LDA + c2] = hi;
            *(uint32_t*)&As[1][r * LDA + c2] = lo;
        }
        // ---- producer: W chunk 32x64 fp32 -> Bs[n][k] hi/lo (1024 pairs) --
        #pragma unroll
        for (int s = 0; s < 4; s++) {
            int p = tid + s * 256;
            int n = p & 63;
            int kk2 = (p >> 6) * 2;
            int gk = k0 + kk2;
            float x0 = (gk < K)     ? __ldg(W + (long long)gk * N + bn + n)       : 0.f;
            float x1 = (gk + 1 < K) ? __ldg(W + (long long)(gk + 1) * N + bn + n) : 0.f;
            uint32_t hi, lo;
            split2(x0, x1, hi, lo);
            *(uint32_t*)&Bs[0][n * LDA + kk2] = hi;
            *(uint32_t*)&Bs[1][n * LDA + kk2] = lo;
        }
        __syncthreads();

        // ---- consumer: 2 x k16 mma steps ----
        #pragma unroll
        for (int ks = 0; ks < 32; ks += 16) {
            uint32_t ah[2][4], al[2][4], bh[4][2], bl[4][2];
            #pragma unroll
            for (int mt = 0; mt < 2; mt++) {
                int r0 = (wm * 32 + mt * 16 + gid) * LDA + ks + 2 * tig;
                ah[mt][0] = *(const uint32_t*)&As[0][r0];
                ah[mt][1] = *(const uint32_t*)&As[0][r0 + 8 * LDA];
                ah[mt][2] = *(const uint32_t*)&As[0][r0 + 8];
                ah[mt][3] = *(const uint32_t*)&As[0][r0 + 8 * LDA + 8];
                al[mt][0] = *(const uint32_t*)&As[1][r0];
                al[mt][1] = *(const uint32_t*)&As[1][r0 + 8 * LDA];
                al[mt][2] = *(const uint32_t*)&As[1][r0 + 8];
                al[mt][3] = *(const uint32_t*)&As[1][r0 + 8 * LDA + 8];
            }
            #pragma unroll
            for (int nt = 0; nt < 4; nt++) {
                int n0 = (wn * 32 + nt * 8 + gid) * LDA + ks + 2 * tig;
                bh[nt][0] = *(const uint32_t*)&Bs[0][n0];
                bh[nt][1] = *(const uint32_t*)&Bs[0][n0 + 8];
                bl[nt][0] = *(const uint32_t*)&Bs[1][n0];
                bl[nt][1] = *(const uint32_t*)&Bs[1][n0 + 8];
            }
            #pragma unroll
            for (int mt = 0; mt < 2; mt++)
                #pragma unroll
                for (int nt = 0; nt < 4; nt++) {
                    MMA_BF16(acc[mt][nt], ah[mt], bh[nt]);
                    MMA_BF16(acc[mt][nt], ah[mt], bl[nt]);
                    MMA_BF16(acc[mt][nt], al[mt], bh[nt]);
                }
        }
        __syncthreads();
    }

    // ---- epilogue: bias + relu, direct coalesced-ish float2 stores ----
    #pragma unroll
    for (int mt = 0; mt < 2; mt++) {
        int r0 = bm + wm * 32 + mt * 16 + gid;
        #pragma unroll
        for (int nt = 0; nt < 4; nt++) {
            int cc = bn + wn * 32 + nt * 8 + tig * 2;
            float b0 = bias[cc], b1 = bias[cc + 1];
            float v00 = acc[mt][nt][0] + b0, v01 = acc[mt][nt][1] + b1;
            float v10 = acc[mt][nt][2] + b0, v11 = acc[mt][nt][3] + b1;
            if (relu) {
                v00 = fmaxf(v00, 0.f); v01 = fmaxf(v01, 0.f);
                v10 = fmaxf(v10, 0.f); v11 = fmaxf(v11, 0.f);
            }
            *(float2*)&C[(long long)r0 * ldc + cc]       = make_float2(v00, v01);
            *(float2*)&C[(long long)(r0 + 8) * ldc + cc] = make_float2(v10, v11);
        }
    }
}

// ---------------- embedding gather + pool: one warp per (f, b) -------------
__global__ __launch_bounds__(256)
void gather_pool(const void* __restrict__ idx_raw,
                 const float* __restrict__ tables,
                 float* __restrict__ feats)
{
    const int gwarp = (blockIdx.x * blockDim.x + threadIdx.x) >> 5;
    const int lane = threadIdx.x & 31;
    if (gwarp >= Fn * Bsz) return;
    const int f = gwarp / Bsz;
    const int b = gwarp % Bsz;

    const long long* p64 = (const long long*)idx_raw;
    long long v0 = p64[0], v1 = p64[123], v2 = p64[4567], v3 = p64[89012];
    const bool is64 = (v0 >= 0 && v0 < Nrows) && (v1 >= 0 && v1 < Nrows) &&
                      (v2 >= 0 && v2 < Nrows) && (v3 >= 0 && v3 < Nrows);
    const int* p32 = (const int*)idx_raw;
    const long long base = (long long)f * Bsz * Lk + (long long)b * Lk;

    float2 acc = make_float2(0.f, 0.f);
    #pragma unroll
    for (int l = 0; l < Lk; l++) {
        long long row = is64 ? p64[base + l] : (long long)p32[base + l];
        const float2* src = (const float2*)(tables + ((long long)f * Nrows + row) * Dim);
        float2 v = src[lane];
        acc.x += v.x; acc.y += v.y;
    }
    float2* dst = (float2*)(feats + (long long)b * (NFEAT * Dim) + (f + 1) * Dim);
    dst[lane] = acc;
}

// ---------------- interaction: triu(feats @ feats^T) -----------------------
__global__ __launch_bounds__(128)
void interact(const float* __restrict__ feats, float* __restrict__ yin)
{
    __shared__ float fs[NFEAT * 68];
    const int b = blockIdx.x;
    const int tid = threadIdx.x;
    const float* frow = feats + (long long)b * (NFEAT * Dim);

    for (int i = tid; i < NFEAT * Dim; i += 128)
        fs[(i >> 6) * 68 + (i & 63)] = frow[i];
    __syncthreads();

    float* yrow = yin + (long long)b * OVERIN;
    for (int i = tid; i < Dim; i += 128) yrow[i] = fs[i];

    for (int p = tid; p < NPAIRS; p += 128) {
        int i = 0, rem = p;
        while (rem >= NFEAT - 1 - i) { rem -= NFEAT - 1 - i; i++; }
        int j = i + 1 + rem;
        const float4* fi = (const float4*)(fs + i * 68);
        const float4* fj = (const float4*)(fs + j * 68);
        float s0 = 0.f, s1 = 0.f;
        #pragma unroll
        for (int k = 0; k < 16; k += 2) {
            float4 a0 = fi[k],     b0v = fj[k];
            float4 a1 = fi[k + 1], b1v = fj[k + 1];
            s0 = fmaf(a0.x, b0v.x, s0); s0 = fmaf(a0.y, b0v.y, s0);
            s0 = fmaf(a0.z, b0v.z, s0); s0 = fmaf(a0.w, b0v.w, s0);
            s1 = fmaf(a1.x, b1v.x, s1); s1 = fmaf(a1.y, b1v.y, s1);
            s1 = fmaf(a1.z, b1v.z, s1); s1 = fmaf(a1.w, b1v.w, s1);
        }
        yrow[Dim + p] = s0 + s1;
    }
}

// ---------------- final layer: (B,256) @ (256,1) + bias --------------------
__global__ __launch_bounds__(256)
void gemv_final(const float* __restrict__ X, const float* __restrict__ w,
                const float* __restrict__ bias, float* __restrict__ out)
{
    const int row = (blockIdx.x * blockDim.x + threadIdx.x) >> 5;
    const int lane = threadIdx.x & 31;
    if (row >= Bsz) return;
    const float4* x = (const float4*)(X + (long long)row * 256);
    const float4* wv = (const float4*)w;
    float s = 0.f;
    #pragma unroll
    for (int k = lane; k < 64; k += 32) {
        float4 a = x[k], c = wv[k];
        s = fmaf(a.x, c.x, s); s = fmaf(a.y, c.y, s);
        s = fmaf(a.z, c.z, s); s = fmaf(a.w, c.w, s);
    }
    #pragma unroll
    for (int o = 16; o; o >>= 1) s += __shfl_down_sync(0xffffffffu, s, o);
    if (lane == 0) out[row] = s + bias[0];
}

// ---------------------------------------------------------------------------
static void* sym_addr(const void* sym)
{
    void* p = nullptr;
    cudaGetSymbolAddress(&p, sym);
    return p;
}

extern "C" void kernel_launch(void* const* d_in, const int* in_sizes, int n_in,
                              void* d_out, int out_size)
{
    (void)in_sizes; (void)n_in; (void)out_size;

    const float* dense   = (const float*)d_in[0];
    const void*  sp_idx  = d_in[1];
    const float* tables  = (const float*)d_in[2];
    const float* botW0   = (const float*)d_in[3];
    const float* botb0   = (const float*)d_in[4];
    const float* botW1   = (const float*)d_in[5];
    const float* botb1   = (const float*)d_in[6];
    const float* botW2   = (const float*)d_in[7];
    const float* botb2   = (const float*)d_in[8];
    const float* topW0   = (const float*)d_in[9];
    const float* topb0   = (const float*)d_in[10];
    const float* topW1   = (const float*)d_in[11];
    const float* topb1   = (const float*)d_in[12];
    const float* topW2   = (const float*)d_in[13];
    const float* topb2   = (const float*)d_in[14];
    float* out = (float*)d_out;

    float* h1    = (float*)sym_addr(g_h1);
    float* h2    = (float*)sym_addr(g_h2);
    float* feats = (float*)sym_addr(g_feats);
    float* yin   = (float*)sym_addr(g_yin);

    const int MB = Bsz / 128;   // 128 M-tiles

    // Embedding gather + pool into feats[:,1..26,:]  (independent of MLPs)
    gather_pool<<<(Fn * Bsz * 32 + 255) / 256, 256>>>(sp_idx, tables, feats);

    // Bottom MLP: 13 -> 512 -> 256 -> 64 (relu each), last into feats[:,0,:]
    gemm_mma<<<dim3(512 / 64, MB), 256>>>(dense, botW0, botb0, h1, 13, 512, 512, 1);
    gemm_mma<<<dim3(256 / 64, MB), 256>>>(h1, botW1, botb1, h2, 512, 256, 256, 1);
    gemm_mma<<<dim3(64 / 64, MB), 256>>>(h2, botW2, botb2, feats, 256, 64,
                                         NFEAT * Dim, 1);

    // Pairwise interaction -> yin (B, 415)
    interact<<<Bsz, 128>>>(feats, yin);

    // Top MLP: 415 -> 512 (relu) -> 256 (relu) -> 1
    gemm_mma<<<dim3(512 / 64, MB), 256>>>(yin, topW0, topb0, h1, OVERIN, 512, 512, 1);
    gemm_mma<<<dim3(256 / 64, MB), 256>>>(h1, topW1, topb1, h2, 512, 256, 256, 1);
    gemv_final<<<(Bsz * 32 + 255) / 256, 256>>>(h2, topW2, topb2, out);
}

// round 5
// speedup vs baseline: 1.5313x; 1.0262x over previous
#include <cuda_runtime.h>
#include <cuda_bf16.h>
#include <cstdint>

#define Bsz 16384
#define Fn 26
#define Nrows 100000
#define Dim 64
#define Lk 4
#define NFEAT 27
#define NPAIRS 351
#define OVERIN 415
#define YSTR 416              // padded OVERIN (multiple of 32)
#define DSTR 32               // padded dense-in (13 -> 32)

// ---------------- scratch (device globals) ----------------------------------
__device__ float g_feats[Bsz * NFEAT * Dim];             // (B, 27, 64) fp32
__device__ __nv_bfloat16 g_dsh[Bsz * DSTR],  g_dsl[Bsz * DSTR];
__device__ __nv_bfloat16 g_h1h[Bsz * 512],   g_h1l[Bsz * 512];
__device__ __nv_bfloat16 g_h2h[Bsz * 256],   g_h2l[Bsz * 256];
__device__ __nv_bfloat16 g_yh[Bsz * YSTR],   g_yl[Bsz * YSTR];
// transposed, K-padded weight planes [N][Kpad]
__device__ __nv_bfloat16 g_w0h[512 * DSTR],  g_w0l[512 * DSTR];
__device__ __nv_bfloat16 g_w1h[256 * 512],   g_w1l[256 * 512];
__device__ __nv_bfloat16 g_w2h[64 * 256],    g_w2l[64 * 256];
__device__ __nv_bfloat16 g_t0h[512 * YSTR],  g_t0l[512 * YSTR];
__device__ __nv_bfloat16 g_t1h[256 * 512],   g_t1l[256 * 512];

// ---------------- helpers ----------------------------------------------------
#define MMA_BF16(c, a, b) \
    asm volatile("mma.sync.aligned.m16n8k16.row.col.f32.bf16.bf16.f32 " \
        "{%0,%1,%2,%3}, {%4,%5,%6,%7}, {%8,%9}, {%0,%1,%2,%3};" \
        : "+f"((c)[0]), "+f"((c)[1]), "+f"((c)[2]), "+f"((c)[3]) \
        : "r"((a)[0]), "r"((a)[1]), "r"((a)[2]), "r"((a)[3]), \
          "r"((b)[0]), "r"((b)[1]))

__device__ __forceinline__ void split1(float x, __nv_bfloat16& h, __nv_bfloat16& l)
{
    h = __float2bfloat16(x);
    l = __float2bfloat16(x - __bfloat162float(h));
}

// ---------------- pre-split kernels -----------------------------------------
__global__ void split_dense(const float* __restrict__ in,
                            __nv_bfloat16* __restrict__ oh,
                            __nv_bfloat16* __restrict__ ol)
{
    int idx = blockIdx.x * blockDim.x + threadIdx.x;
    if (idx >= Bsz * DSTR) return;
    int b = idx >> 5, k = idx & 31;
    float v = (k < 13) ? in[b * 13 + k] : 0.f;
    split1(v, oh[idx], ol[idx]);
}

// W (K x N, row-major) -> planes [N][Kpad], zero-padded
__global__ void split_wt(const float* __restrict__ W, int K, int N, int Kpad,
                         __nv_bfloat16* __restrict__ oh,
                         __nv_bfloat16* __restrict__ ol)
{
    int idx = blockIdx.x * blockDim.x + threadIdx.x;
    if (idx >= N * Kpad) return;
    int n = idx / Kpad, k = idx % Kpad;
    float v = (k < K) ? W[(long long)k * N + n] : 0.f;
    split1(v, oh[idx], ol[idx]);
}

// ============ bf16 tensor-core GEMM over pre-split planes ====================
// CTA 128x64, 8 warps (4M x 2N), warp 32x32, K-chunk 32, reg-prefetch pipeline.
#define LDA 40

__global__ __launch_bounds__(256)
void gemm_bf16(const __nv_bfloat16* __restrict__ Ah,
               const __nv_bfloat16* __restrict__ Al,
               const __nv_bfloat16* __restrict__ Bh,
               const __nv_bfloat16* __restrict__ Bl,
               const float* __restrict__ bias, int K, int relu, int outmode,
               float* __restrict__ Cf, int ldcf,
               __nv_bfloat16* __restrict__ Ch, __nv_bfloat16* __restrict__ Cl,
               int ldcb)
{
    __shared__ __align__(16) __nv_bfloat16 As[2][128 * LDA];
    __shared__ __align__(16) __nv_bfloat16 Bs[2][64 * LDA];

    const int tid  = threadIdx.x;
    const int warp = tid >> 5, lane = tid & 31;
    const int wm = warp & 3, wn = warp >> 2;
    const int gid = lane >> 2, tig = lane & 3;
    const int bm = blockIdx.y * 128, bn = blockIdx.x * 64;

    float acc[2][4][4];
    #pragma unroll
    for (int mt = 0; mt < 2; mt++)
        #pragma unroll
        for (int nt = 0; nt < 4; nt++)
            #pragma unroll
            for (int e = 0; e < 4; e++) acc[mt][nt][e] = 0.f;

    const int kIter = K >> 5;           // K is a multiple of 32, zero-padded
    uint4 pa[4], pb[2];

    auto prefetch = [&](int it) {
        const int k0 = it * 32;
        #pragma unroll
        for (int s = 0; s < 4; s++) {
            int idx = tid + s * 256;
            int pl = idx >> 9, rem = idx & 511, r = rem >> 2, kq = rem & 3;
            const __nv_bfloat16* src = (pl ? Al : Ah) +
                (long long)(bm + r) * K + k0 + kq * 8;
            pa[s] = *(const uint4*)src;
        }
        #pragma unroll
        for (int s = 0; s < 2; s++) {
            int idx = tid + s * 256;
            int pl = idx >> 8, rem = idx & 255, n = rem >> 2, kq = rem & 3;
            const __nv_bfloat16* src = (pl ? Bl : Bh) +
                (long long)(bn + n) * K + k0 + kq * 8;
            pb[s] = *(const uint4*)src;
        }
    };

    prefetch(0);
    for (int it = 0; it < kIter; it++) {
        if (it) __syncthreads();        // smem consumed by previous mma block
        #pragma unroll
        for (int s = 0; s < 4; s++) {
            int idx = tid + s * 256;
            int pl = idx >> 9, rem = idx & 511, r = rem >> 2, kq = rem & 3;
            *(uint4*)&As[pl][r * LDA + kq * 8] = pa[s];
        }
        #pragma unroll
        for (int s = 0; s < 2; s++) {
            int idx = tid + s * 256;
            int pl = idx >> 8, rem = idx & 255, n = rem >> 2, kq = rem & 3;
            *(uint4*)&Bs[pl][n * LDA + kq * 8] = pb[s];
        }
        __syncthreads();
        if (it + 1 < kIter) prefetch(it + 1);   // overlap with mma below

        #pragma unroll
        for (int ks = 0; ks < 32; ks += 16) {
            uint32_t ah[2][4], al[2][4], bh[4][2], bl[4][2];
            #pragma unroll
            for (int mt = 0; mt < 2; mt++) {
                int r0 = (wm * 32 + mt * 16 + gid) * LDA + ks + 2 * tig;
                ah[mt][0] = *(const uint32_t*)&As[0][r0];
                ah[mt][1] = *(const uint32_t*)&As[0][r0 + 8 * LDA];
                ah[mt][2] = *(const uint32_t*)&As[0][r0 + 8];
                ah[mt][3] = *(const uint32_t*)&As[0][r0 + 8 * LDA + 8];
                al[mt][0] = *(const uint32_t*)&As[1][r0];
                al[mt][1] = *(const uint32_t*)&As[1][r0 + 8 * LDA];
                al[mt][2] = *(const uint32_t*)&As[1][r0 + 8];
                al[mt][3] = *(const uint32_t*)&As[1][r0 + 8 * LDA + 8];
            }
            #pragma unroll
            for (int nt = 0; nt < 4; nt++) {
                int n0 = (wn * 32 + nt * 8 + gid) * LDA + ks + 2 * tig;
                bh[nt][0] = *(const uint32_t*)&Bs[0][n0];
                bh[nt][1] = *(const uint32_t*)&Bs[0][n0 + 8];
                bl[nt][0] = *(const uint32_t*)&Bs[1][n0];
                bl[nt][1] = *(const uint32_t*)&Bs[1][n0 + 8];
            }
            #pragma unroll
            for (int mt = 0; mt < 2; mt++)
                #pragma unroll
                for (int nt = 0; nt < 4; nt++) {
                    MMA_BF16(acc[mt][nt], ah[mt], bh[nt]);
                    MMA_BF16(acc[mt][nt], ah[mt], bl[nt]);
                    MMA_BF16(acc[mt][nt], al[mt], bh[nt]);
                }
        }
    }

    // ---- epilogue ----
    #pragma unroll
    for (int mt = 0; mt < 2; mt++) {
        int r0 = bm + wm * 32 + mt * 16 + gid;
        #pragma unroll
        for (int nt = 0; nt < 4; nt++) {
            int cc = bn + wn * 32 + nt * 8 + tig * 2;
            float b0 = bias[cc], b1 = bias[cc + 1];
            float v00 = acc[mt][nt][0] + b0, v01 = acc[mt][nt][1] + b1;
            float v10 = acc[mt][nt][2] + b0, v11 = acc[mt][nt][3] + b1;
            if (relu) {
                v00 = fmaxf(v00, 0.f); v01 = fmaxf(v01, 0.f);
                v10 = fmaxf(v10, 0.f); v11 = fmaxf(v11, 0.f);
            }
            if (outmode == 0) {
                *(float2*)&Cf[(long long)r0 * ldcf + cc]       = make_float2(v00, v01);
                *(float2*)&Cf[(long long)(r0 + 8) * ldcf + cc] = make_float2(v10, v11);
            } else {
                __nv_bfloat162 h0, l0, h1v, l1v;
                split1(v00, h0.x, l0.x);  split1(v01, h0.y, l0.y);
                split1(v10, h1v.x, l1v.x); split1(v11, h1v.y, l1v.y);
                *(uint32_t*)&Ch[(long long)r0 * ldcb + cc]       = *(uint32_t*)&h0;
                *(uint32_t*)&Cl[(long long)r0 * ldcb + cc]       = *(uint32_t*)&l0;
                *(uint32_t*)&Ch[(long long)(r0 + 8) * ldcb + cc] = *(uint32_t*)&h1v;
                *(uint32_t*)&Cl[(long long)(r0 + 8) * ldcb + cc] = *(uint32_t*)&l1v;
            }
        }
    }
}

// ---------------- embedding gather + pool: one warp per (f, b) --------------
__global__ __launch_bounds__(256)
void gather_pool(const void* __restrict__ idx_raw,
                 const float* __restrict__ tables,
                 float* __restrict__ feats)
{
    const int gwarp = (blockIdx.x * blockDim.x + threadIdx.x) >> 5;
    const int lane = threadIdx.x & 31;
    if (gwarp >= Fn * Bsz) return;
    const int f = gwarp / Bsz;
    const int b = gwarp % Bsz;

    const long long* p64 = (const long long*)idx_raw;
    long long v0 = p64[0], v1 = p64[123], v2 = p64[4567], v3 = p64[89012];
    const bool is64 = (v0 >= 0 && v0 < Nrows) && (v1 >= 0 && v1 < Nrows) &&
                      (v2 >= 0 && v2 < Nrows) && (v3 >= 0 && v3 < Nrows);
    const int* p32 = (const int*)idx_raw;
    const long long base = (long long)f * Bsz * Lk + (long long)b * Lk;

    float2 acc = make_float2(0.f, 0.f);
    #pragma unroll
    for (int l = 0; l < Lk; l++) {
        long long row = is64 ? p64[base + l] : (long long)p32[base + l];
        const float2* src = (const float2*)(tables + ((long long)f * Nrows + row) * Dim);
        float2 v = src[lane];
        acc.x += v.x; acc.y += v.y;
    }
    float2* dst = (float2*)(feats + (long long)b * (NFEAT * Dim) + (f + 1) * Dim);
    dst[lane] = acc;
}

// ---------------- interaction -> padded bf16 planes -------------------------
__global__ __launch_bounds__(128)
void interact(const float* __restrict__ feats,
              __nv_bfloat16* __restrict__ yh, __nv_bfloat16* __restrict__ yl)
{
    __shared__ float fs[NFEAT * 68];
    const int b = blockIdx.x;
    const int tid = threadIdx.x;
    const float* frow = feats + (long long)b * (NFEAT * Dim);

    for (int i = tid; i < NFEAT * Dim; i += 128)
        fs[(i >> 6) * 68 + (i & 63)] = frow[i];
    __syncthreads();

    __nv_bfloat16* yrh = yh + (long long)b * YSTR;
    __nv_bfloat16* yrl = yl + (long long)b * YSTR;
    for (int i = tid; i < Dim; i += 128) split1(fs[i], yrh[i], yrl[i]);
    if (tid == 0) { yrh[OVERIN] = __float2bfloat16(0.f);
                    yrl[OVERIN] = __float2bfloat16(0.f); }

    for (int p = tid; p < NPAIRS; p += 128) {
        int i = 0, rem = p;
        while (rem >= NFEAT - 1 - i) { rem -= NFEAT - 1 - i; i++; }
        int j = i + 1 + rem;
        const float4* fi = (const float4*)(fs + i * 68);
        const float4* fj = (const float4*)(fs + j * 68);
        float s0 = 0.f, s1 = 0.f;
        #pragma unroll
        for (int k = 0; k < 16; k += 2) {
            float4 a0 = fi[k],     b0v = fj[k];
            float4 a1 = fi[k + 1], b1v = fj[k + 1];
            s0 = fmaf(a0.x, b0v.x, s0); s0 = fmaf(a0.y, b0v.y, s0);
            s0 = fmaf(a0.z, b0v.z, s0); s0 = fmaf(a0.w, b0v.w, s0);
            s1 = fmaf(a1.x, b1v.x, s1); s1 = fmaf(a1.y, b1v.y, s1);
            s1 = fmaf(a1.z, b1v.z, s1); s1 = fmaf(a1.w, b1v.w, s1);
        }
        split1(s0 + s1, yrh[Dim + p], yrl[Dim + p]);
    }
}

// ---------------- final layer over planes: (B,256) @ (256,1) + bias ---------
__global__ __launch_bounds__(256)
void gemv_final(const __nv_bfloat16* __restrict__ Xh,
                const __nv_bfloat16* __restrict__ Xl,
                const float* __restrict__ w,
                const float* __restrict__ bias, float* __restrict__ out)
{
    const int row = (blockIdx.x * blockDim.x + threadIdx.x) >> 5;
    const int lane = threadIdx.x & 31;
    if (row >= Bsz) return;
    uint4 hv = *(const uint4*)(Xh + (long long)row * 256 + lane * 8);
    uint4 lv = *(const uint4*)(Xl + (long long)row * 256 + lane * 8);
    const __nv_bfloat162* hp = (const __nv_bfloat162*)&hv;
    const __nv_bfloat162* lp = (const __nv_bfloat162*)&lv;
    float s = 0.f;
    #pragma unroll
    for (int q = 0; q < 4; q++) {
        float2 h2 = __bfloat1622float2(hp[q]);
        float2 l2 = __bfloat1622float2(lp[q]);
        float w0 = w[lane * 8 + q * 2], w1 = w[lane * 8 + q * 2 + 1];
        s = fmaf(h2.x + l2.x, w0, s);
        s = fmaf(h2.y + l2.y, w1, s);
    }
    #pragma unroll
    for (int o = 16; o; o >>= 1) s += __shfl_down_sync(0xffffffffu, s, o);
    if (lane == 0) out[row] = s + bias[0];
}

// -----------------------------------------------------------------------------
static void* sym_addr(const void* sym)
{
    void* p = nullptr;
    cudaGetSymbolAddress(&p, sym);
    return p;
}

extern "C" void kernel_launch(void* const* d_in, const int* in_sizes, int n_in,
                              void* d_out, int out_size)
{
    (void)in_sizes; (void)n_in; (void)out_size;

    const float* dense   = (const float*)d_in[0];
    const void*  sp_idx  = d_in[1];
    const float* tables  = (const float*)d_in[2];
    const float* botW0   = (const float*)d_in[3];
    const float* botb0   = (const float*)d_in[4];
    const float* botW1   = (const float*)d_in[5];
    const float* botb1   = (const float*)d_in[6];
    const float* botW2   = (const float*)d_in[7];
    const float* botb2   = (const float*)d_in[8];
    const float* topW0   = (const float*)d_in[9];
    const float* topb0   = (const float*)d_in[10];
    const float* topW1   = (const float*)d_in[11];
    const float* topb1   = (const float*)d_in[12];
    const float* topW2   = (const float*)d_in[13];
    const float* topb2   = (const float*)d_in[14];
    float* out = (float*)d_out;

    float* feats = (float*)sym_addr(g_feats);
    __nv_bfloat16* dsh = (__nv_bfloat16*)sym_addr(g_dsh);
    __nv_bfloat16* dsl = (__nv_bfloat16*)sym_addr(g_dsl);
    __nv_bfloat16* h1h = (__nv_bfloat16*)sym_addr(g_h1h);
    __nv_bfloat16* h1l = (__nv_bfloat16*)sym_addr(g_h1l);
    __nv_bfloat16* h2h = (__nv_bfloat16*)sym_addr(g_h2h);
    __nv_bfloat16* h2l = (__nv_bfloat16*)sym_addr(g_h2l);
    __nv_bfloat16* yh  = (__nv_bfloat16*)sym_addr(g_yh);
    __nv_bfloat16* yl  = (__nv_bfloat16*)sym_addr(g_yl);
    __nv_bfloat16* w0h = (__nv_bfloat16*)sym_addr(g_w0h);
    __nv_bfloat16* w0l = (__nv_bfloat16*)sym_addr(g_w0l);
    __nv_bfloat16* w1h = (__nv_bfloat16*)sym_addr(g_w1h);
    __nv_bfloat16* w1l = (__nv_bfloat16*)sym_addr(g_w1l);
    __nv_bfloat16* w2h = (__nv_bfloat16*)sym_addr(g_w2h);
    __nv_bfloat16* w2l = (__nv_bfloat16*)sym_addr(g_w2l);
    __nv_bfloat16* t0h = (__nv_bfloat16*)sym_addr(g_t0h);
    __nv_bfloat16* t0l = (__nv_bfloat16*)sym_addr(g_t0l);
    __nv_bfloat16* t1h = (__nv_bfloat16*)sym_addr(g_t1h);
    __nv_bfloat16* t1l = (__nv_bfloat16*)sym_addr(g_t1l);

    const int MB = Bsz / 128;

    // --- pre-split weights (tiny) + dense input ---
    split_wt<<<(512 * DSTR + 255) / 256, 256>>>(botW0, 13, 512, DSTR, w0h, w0l);
    split_wt<<<(256 * 512 + 255) / 256, 256>>>(botW1, 512, 256, 512, w1h, w1l);
    split_wt<<<(64 * 256 + 255) / 256, 256>>>(botW2, 256, 64, 256, w2h, w2l);
    split_wt<<<(512 * YSTR + 255) / 256, 256>>>(topW0, OVERIN, 512, YSTR, t0h, t0l);
    split_wt<<<(256 * 512 + 255) / 256, 256>>>(topW1, 512, 256, 512, t1h, t1l);
    split_dense<<<(Bsz * DSTR + 255) / 256, 256>>>(dense, dsh, dsl);

    // --- embedding gather + pool (independent) ---
    gather_pool<<<(Fn * Bsz * 32 + 255) / 256, 256>>>(sp_idx, tables, feats);

    // --- bottom MLP ---
    gemm_bf16<<<dim3(8, MB), 256>>>(dsh, dsl, w0h, w0l, botb0, DSTR, 1, 1,
                                    nullptr, 0, h1h, h1l, 512);
    gemm_bf16<<<dim3(4, MB), 256>>>(h1h, h1l, w1h, w1l, botb1, 512, 1, 1,
                                    nullptr, 0, h2h, h2l, 256);
    gemm_bf16<<<dim3(1, MB), 256>>>(h2h, h2l, w2h, w2l, botb2, 256, 1, 0,
                                    feats, NFEAT * Dim, nullptr, nullptr, 0);

    // --- interaction ---
    interact<<<Bsz, 128>>>(feats, yh, yl);

    // --- top MLP ---
    gemm_bf16<<<dim3(8, MB), 256>>>(yh, yl, t0h, t0l, topb0, YSTR, 1, 1,
                                    nullptr, 0, h1h, h1l, 512);
    gemm_bf16<<<dim3(4, MB), 256>>>(h1h, h1l, t1h, t1l, topb1, 512, 1, 1,
                                    nullptr, 0, h2h, h2l, 256);
    gemv_final<<<(Bsz * 32 + 255) / 256, 256>>>(h2h, h2l, topW2, topb2, out);
}